// round 4
// baseline (speedup 1.0000x reference)
#include <cuda_runtime.h>
#include <cstdint>

// 2x nearest-neighbor upsample — OUTPUT-centric, perfect store contiguity.
// in : [16, 64, 256, 256] fp32
// out: [16, 64, 512, 512] fp32
//
// One thread per 32-byte output chunk (8 consecutive output floats):
//   - consecutive threads write consecutive addresses -> each warp store
//     instruction covers one fully-populated contiguous 1 KB span.
//   - each thread loads the matching 16-byte input chunk (4 floats) via the
//     non-coherent path; the duplicate-row re-read hits L2.

static constexpr int W8_OUT = 64;   // 8-float chunks per output row (512/8)
static constexpr int W_IN   = 256;  // floats per input row

__global__ __launch_bounds__(256)
void upsample2x_oc_kernel(const float* __restrict__ in,
                          float* __restrict__ out,
                          int n_out8)
{
    int o8 = blockIdx.x * blockDim.x + threadIdx.x;
    if (o8 >= n_out8) return;

    int ocol8 = o8 & (W8_OUT - 1);   // output 8-chunk within row
    int orow  = o8 >> 6;             // global output row (b*c*2h + r)
    int irow  = orow >> 1;           // source input row

    const float* ip = in + (size_t)irow * W_IN + (size_t)ocol8 * 4;

    float f0, f1, f2, f3;
    asm volatile(
        "ld.global.nc.v4.f32 {%0,%1,%2,%3}, [%4];"
        : "=f"(f0), "=f"(f1), "=f"(f2), "=f"(f3)
        : "l"(ip));

    float* op = out + (size_t)o8 * 8;
    asm volatile(
        "st.global.cs.v8.f32 [%0], {%1,%2,%3,%4,%5,%6,%7,%8};"
        :: "l"(op),
           "f"(f0), "f"(f0), "f"(f1), "f"(f1),
           "f"(f2), "f"(f2), "f"(f3), "f"(f3)
        : "memory");
}

extern "C" void kernel_launch(void* const* d_in, const int* in_sizes, int n_in,
                              void* d_out, int out_size)
{
    const float* in  = (const float*)d_in[0];
    float*       out = (float*)d_out;

    int n_out8 = out_size / 8;          // 16*64*512*512/8 = 33554432

    int threads = 256;
    int blocks  = (n_out8 + threads - 1) / threads;
    upsample2x_oc_kernel<<<blocks, threads>>>(in, out, n_out8);
}

// round 5
// speedup vs baseline: 1.0103x; 1.0103x over previous
#include <cuda_runtime.h>
#include <cstdint>

// 2x nearest-neighbor upsample — best variant (R2 structure) + nc load,
// 512-thread blocks.
// in : [16, 64, 256, 256] fp32 = 67108864 floats
// out: [16, 64, 512, 512] fp32
//
// One thread per 32-byte input chunk (8 consecutive input pixels along W):
//   1 x ld.global.nc.v8.f32  +  4 x st.global.v8.f32
// producing a 16-pixel x 2-row output patch.

static constexpr int W8_IN = 32;   // 8-float chunks per input row (256/8)
static constexpr int W_OUT = 512;  // floats per output row

__global__ __launch_bounds__(512)
void upsample2x_v8_kernel(const float* __restrict__ in,
                          float* __restrict__ out,
                          int n8)
{
    int idx = blockIdx.x * blockDim.x + threadIdx.x;
    if (idx >= n8) return;

    int row  = idx >> 5;          // idx / 32  (combined b*c*h row index)
    int col8 = idx & (W8_IN - 1); // idx % 32

    const float* ip = in + (size_t)idx * 8;

    float f0, f1, f2, f3, f4, f5, f6, f7;
    asm volatile(
        "ld.global.nc.v8.f32 {%0,%1,%2,%3,%4,%5,%6,%7}, [%8];"
        : "=f"(f0), "=f"(f1), "=f"(f2), "=f"(f3),
          "=f"(f4), "=f"(f5), "=f"(f6), "=f"(f7)
        : "l"(ip));

    float* op = out + (size_t)(row * 2) * W_OUT + (size_t)col8 * 16;

    // Row 0: [f0 f0 f1 f1 f2 f2 f3 f3][f4 f4 f5 f5 f6 f6 f7 f7]
    asm volatile(
        "st.global.v8.f32 [%0], {%1,%2,%3,%4,%5,%6,%7,%8};"
        :: "l"(op),
           "f"(f0), "f"(f0), "f"(f1), "f"(f1),
           "f"(f2), "f"(f2), "f"(f3), "f"(f3) : "memory");
    asm volatile(
        "st.global.v8.f32 [%0], {%1,%2,%3,%4,%5,%6,%7,%8};"
        :: "l"(op + 8),
           "f"(f4), "f"(f4), "f"(f5), "f"(f5),
           "f"(f6), "f"(f6), "f"(f7), "f"(f7) : "memory");
    // Row 1 = duplicate of row 0
    asm volatile(
        "st.global.v8.f32 [%0], {%1,%2,%3,%4,%5,%6,%7,%8};"
        :: "l"(op + W_OUT),
           "f"(f0), "f"(f0), "f"(f1), "f"(f1),
           "f"(f2), "f"(f2), "f"(f3), "f"(f3) : "memory");
    asm volatile(
        "st.global.v8.f32 [%0], {%1,%2,%3,%4,%5,%6,%7,%8};"
        :: "l"(op + W_OUT + 8),
           "f"(f4), "f"(f4), "f"(f5), "f"(f5),
           "f"(f6), "f"(f6), "f"(f7), "f"(f7) : "memory");
}

extern "C" void kernel_launch(void* const* d_in, const int* in_sizes, int n_in,
                              void* d_out, int out_size)
{
    const float* in  = (const float*)d_in[0];
    float*       out = (float*)d_out;

    int n_elems = in_sizes[0];          // 67108864
    int n8      = n_elems / 8;          // 8388608 threads

    int threads = 512;
    int blocks  = (n8 + threads - 1) / threads;
    upsample2x_v8_kernel<<<blocks, threads>>>(in, out, n8);
}